// round 4
// baseline (speedup 1.0000x reference)
#include <cuda_runtime.h>
#include <cuda_bf16.h>
#include <math.h>

// Problem constants
#define NN    4096          // graph nodes
#define TT    48            // timesteps
#define HH    64            // hidden
#define INW   2             // input width
#define PP    12            // output width
#define G4    256           // 4*H
#define RTILE 32            // rows per block in cell kernels

#define NNZ_MAX (1 << 19)   // expected ~172k nnz (1% density + diag); 512k is ample

// ---------------- device scratch (static: allocation rules forbid cudaMalloc) ----
__device__ int   g_rowptr[NN + 1];
__device__ int   g_rowcnt[NN];
__device__ int   g_col[NNZ_MAX];
__device__ float g_val[NNZ_MAX];
__device__ float g_dinv[NN];
__device__ float g_xT[NN * 96];   // x transposed: [node][t*2+c]
__device__ float g_AX[NN * 96];   // A @ x, same layout
__device__ float g_h0[2][NN * HH];
__device__ float g_c0[2][NN * HH];
__device__ float g_h1[2][NN * HH];
__device__ float g_c1[2][NN * HH];

__device__ __forceinline__ float sigm(float x) { return 1.0f / (1.0f + expf(-x)); }

// ---------------- preprocessing -------------------------------------------------

// Per-row degree (of adj + I) and nnz count.
__global__ void degree_kernel(const float* __restrict__ adj) {
    const int i = blockIdx.x;
    const int tid = threadIdx.x;
    const float* row = adj + (size_t)i * NN;
    float d = 0.0f;
    int cnt = 0;
    for (int j = tid; j < NN; j += blockDim.x) {
        const float a = __ldg(&row[j]);
        d += a;
        cnt += (a != 0.0f && j != i) ? 1 : 0;
    }
    __shared__ float sd[128];
    __shared__ int   sc[128];
    sd[tid] = d; sc[tid] = cnt;
    __syncthreads();
    for (int off = 64; off > 0; off >>= 1) {
        if (tid < off) { sd[tid] += sd[tid + off]; sc[tid] += sc[tid + off]; }
        __syncthreads();
    }
    if (tid == 0) {
        const float dd = sd[0] + 1.0f;            // + self loop
        g_dinv[i]   = 1.0f / sqrtf(dd);
        g_rowcnt[i] = sc[0] + 1;                  // + diagonal entry
    }
}

// Exclusive scan of 4096 row counts -> rowptr. One block, 1024 threads x 4 items.
__global__ void scan_kernel() {
    __shared__ int s[1024];
    const int tid = threadIdx.x;
    int c[4];
    int sum = 0;
#pragma unroll
    for (int u = 0; u < 4; ++u) { c[u] = g_rowcnt[tid * 4 + u]; sum += c[u]; }
    s[tid] = sum;
    __syncthreads();
    for (int off = 1; off < 1024; off <<= 1) {
        const int v = (tid >= off) ? s[tid - off] : 0;
        __syncthreads();
        s[tid] += v;
        __syncthreads();
    }
    int excl = s[tid] - sum;
#pragma unroll
    for (int u = 0; u < 4; ++u) { g_rowptr[tid * 4 + u] = excl; excl += c[u]; }
    if (tid == 1023) g_rowptr[NN] = s[1023];
}

// One warp per row: compact nonzeros (plus diagonal) into CSR with normalized values.
__global__ void fill_kernel(const float* __restrict__ adj) {
    const int w = (blockIdx.x * blockDim.x + threadIdx.x) >> 5;
    const int lane = threadIdx.x & 31;
    if (w >= NN) return;
    const int i = w;
    const float* row = adj + (size_t)i * NN;
    const float di = g_dinv[i];
    int base = g_rowptr[i];
    for (int j0 = 0; j0 < NN; j0 += 32) {
        const int j = j0 + lane;
        const float a = __ldg(&row[j]);
        const bool pred = (a != 0.0f) || (j == i);
        const unsigned mask = __ballot_sync(0xffffffffu, pred);
        if (pred) {
            const int idx = base + __popc(mask & ((1u << lane) - 1u));
            if (idx < NNZ_MAX) {
                g_col[idx] = j;
                const float v = a + ((j == i) ? 1.0f : 0.0f);
                g_val[idx] = di * g_dinv[j] * v;
            }
        }
        base += __popc(mask);
    }
}

// Transpose x: [t][n][c] -> [n][t*2+c]
__global__ void xT_kernel(const float* __restrict__ x) {
    const int idx = blockIdx.x * blockDim.x + threadIdx.x;
    if (idx >= NN * 96) return;
    const int n = idx / 96;
    const int k = idx % 96;
    const int t = k >> 1;
    const int c = k & 1;
    g_xT[idx] = __ldg(&x[t * (NN * INW) + n * INW + c]);
}

// AX = A @ xT  (96 columns at once, once per launch)
__global__ void ax_kernel() {
    const int i = blockIdx.x;
    const int k = threadIdx.x;  // 0..95
    const int p0 = g_rowptr[i], p1 = g_rowptr[i + 1];
    float acc = 0.0f;
    for (int p = p0; p < p1; ++p)
        acc = fmaf(g_val[p], g_xT[g_col[p] * 96 + k], acc);
    g_AX[i * 96 + k] = acc;
}

__global__ void zero_kernel() {
    const int idx = blockIdx.x * blockDim.x + threadIdx.x;
    if (idx < NN * HH) {
        g_h0[0][idx] = 0.0f; g_c0[0][idx] = 0.0f;
        g_h1[0][idx] = 0.0f; g_c1[0][idx] = 0.0f;
    }
}

// ---------------- fused cell kernels --------------------------------------------
// Block: 256 threads, RTILE=32 rows.
// Phase A: gather A@h (and A@inp for cell1) into smem, copy local rows.
// Phase B: thread (kk = tid&63, rg = tid>>6) accumulates gate columns
//          kk, kk+64, kk+128, kk+192 for 8 rows -> gates computed in registers.

__global__ void __launch_bounds__(256, 2) cell0_kernel(
    int t, int rd,
    const float* __restrict__ Wgi, const float* __restrict__ Wgh,
    const float* __restrict__ Wli, const float* __restrict__ Wlh,
    const float* __restrict__ bgi, const float* __restrict__ bgh,
    const float* __restrict__ bli, const float* __restrict__ blh)
{
    __shared__ float sAh[RTILE][HH];
    __shared__ float sH [RTILE][HH];
    __shared__ float sXA[RTILE][2];
    __shared__ float sXI[RTILE][2];

    const float* __restrict__ h_in = g_h0[rd];
    const float* __restrict__ c_in = g_c0[rd];
    float* __restrict__ h_out = g_h0[rd ^ 1];
    float* __restrict__ c_out = g_c0[rd ^ 1];

    const int tid = threadIdx.x;
    const int m   = tid & 63;
    const int rg  = tid >> 6;
    const int row0 = blockIdx.x * RTILE;

    for (int r = rg; r < RTILE; r += 4) {
        const int i = row0 + r;
        sH[r][m] = __ldg(&h_in[i * HH + m]);
        float acc = 0.0f;
        const int p0 = g_rowptr[i];
        const int p1 = g_rowptr[i + 1];
        // software-pipelined gather (2-deep) to expose MLP
        int p = p0;
        if (p < p1) {
            float v = g_val[p];
            int   c = g_col[p];
            for (++p; p < p1; ++p) {
                const float vn = g_val[p];
                const int   cn = g_col[p];
                acc = fmaf(v, __ldg(&h_in[c * HH + m]), acc);
                v = vn; c = cn;
            }
            acc = fmaf(v, __ldg(&h_in[c * HH + m]), acc);
        }
        sAh[r][m] = acc;
        if (m < 2) {
            sXA[r][m] = g_AX[i * 96 + 2 * t + m];
            sXI[r][m] = g_xT[i * 96 + 2 * t + m];
        }
    }
    __syncthreads();

    const int kk = m;
    const int rbase = rg * 8;

    float ai[8], af[8], ao[8], ag[8];
    {
        const float b0 = __ldg(&bgi[kk      ]) + __ldg(&bgh[kk      ]) + __ldg(&bli[kk      ]) + __ldg(&blh[kk      ]);
        const float b1 = __ldg(&bgi[kk +  64]) + __ldg(&bgh[kk +  64]) + __ldg(&bli[kk +  64]) + __ldg(&blh[kk +  64]);
        const float b2 = __ldg(&bgi[kk + 128]) + __ldg(&bgh[kk + 128]) + __ldg(&bli[kk + 128]) + __ldg(&blh[kk + 128]);
        const float b3 = __ldg(&bgi[kk + 192]) + __ldg(&bgh[kk + 192]) + __ldg(&bli[kk + 192]) + __ldg(&blh[kk + 192]);
#pragma unroll
        for (int r = 0; r < 8; ++r) { ai[r] = b0; af[r] = b1; ao[r] = b2; ag[r] = b3; }
    }

#pragma unroll 4
    for (int mm = 0; mm < HH; ++mm) {
        const float w0 = __ldg(&Wgh[mm * G4 + kk      ]);
        const float w1 = __ldg(&Wgh[mm * G4 + kk +  64]);
        const float w2 = __ldg(&Wgh[mm * G4 + kk + 128]);
        const float w3 = __ldg(&Wgh[mm * G4 + kk + 192]);
#pragma unroll
        for (int r = 0; r < 8; ++r) {
            const float v = sAh[rbase + r][mm];
            ai[r] = fmaf(v, w0, ai[r]); af[r] = fmaf(v, w1, af[r]);
            ao[r] = fmaf(v, w2, ao[r]); ag[r] = fmaf(v, w3, ag[r]);
        }
    }
#pragma unroll 4
    for (int mm = 0; mm < HH; ++mm) {
        const float w0 = __ldg(&Wlh[mm * G4 + kk      ]);
        const float w1 = __ldg(&Wlh[mm * G4 + kk +  64]);
        const float w2 = __ldg(&Wlh[mm * G4 + kk + 128]);
        const float w3 = __ldg(&Wlh[mm * G4 + kk + 192]);
#pragma unroll
        for (int r = 0; r < 8; ++r) {
            const float v = sH[rbase + r][mm];
            ai[r] = fmaf(v, w0, ai[r]); af[r] = fmaf(v, w1, af[r]);
            ao[r] = fmaf(v, w2, ao[r]); ag[r] = fmaf(v, w3, ag[r]);
        }
    }
#pragma unroll
    for (int mm = 0; mm < INW; ++mm) {
        const float w0 = __ldg(&Wgi[mm * G4 + kk      ]);
        const float w1 = __ldg(&Wgi[mm * G4 + kk +  64]);
        const float w2 = __ldg(&Wgi[mm * G4 + kk + 128]);
        const float w3 = __ldg(&Wgi[mm * G4 + kk + 192]);
        const float u0 = __ldg(&Wli[mm * G4 + kk      ]);
        const float u1 = __ldg(&Wli[mm * G4 + kk +  64]);
        const float u2 = __ldg(&Wli[mm * G4 + kk + 128]);
        const float u3 = __ldg(&Wli[mm * G4 + kk + 192]);
#pragma unroll
        for (int r = 0; r < 8; ++r) {
            const float va = sXA[rbase + r][mm];
            const float vi = sXI[rbase + r][mm];
            ai[r] = fmaf(va, w0, ai[r]); af[r] = fmaf(va, w1, af[r]);
            ao[r] = fmaf(va, w2, ao[r]); ag[r] = fmaf(va, w3, ag[r]);
            ai[r] = fmaf(vi, u0, ai[r]); af[r] = fmaf(vi, u1, af[r]);
            ao[r] = fmaf(vi, u2, ao[r]); ag[r] = fmaf(vi, u3, ag[r]);
        }
    }

#pragma unroll
    for (int r = 0; r < 8; ++r) {
        const int i = row0 + rbase + r;
        const float cold = __ldg(&c_in[i * HH + kk]);
        const float igt = sigm(ai[r]);
        const float fgt = sigm(af[r]);
        const float ogt = sigm(ao[r]);
        const float ggt = tanhf(ag[r]);
        const float cn = fgt * cold + igt * ggt;
        c_out[i * HH + kk] = cn;
        h_out[i * HH + kk] = ogt * tanhf(cn);
    }
}

__global__ void __launch_bounds__(256, 2) cell1_kernel(
    int rd,
    const float* __restrict__ Wgi, const float* __restrict__ Wgh,
    const float* __restrict__ Wli, const float* __restrict__ Wlh,
    const float* __restrict__ bgi, const float* __restrict__ bgh,
    const float* __restrict__ bli, const float* __restrict__ blh)
{
    __shared__ float sAi[RTILE][HH];
    __shared__ float sAh[RTILE][HH];
    __shared__ float sI [RTILE][HH];
    __shared__ float sH [RTILE][HH];

    const float* __restrict__ inp  = g_h0[rd ^ 1];   // h0_new, written by cell0 this step
    const float* __restrict__ h_in = g_h1[rd];
    const float* __restrict__ c_in = g_c1[rd];
    float* __restrict__ h_out = g_h1[rd ^ 1];
    float* __restrict__ c_out = g_c1[rd ^ 1];

    const int tid = threadIdx.x;
    const int m   = tid & 63;
    const int rg  = tid >> 6;
    const int row0 = blockIdx.x * RTILE;

    for (int r = rg; r < RTILE; r += 4) {
        const int i = row0 + r;
        sI[r][m] = __ldg(&inp[i * HH + m]);
        sH[r][m] = __ldg(&h_in[i * HH + m]);
        float a0 = 0.0f, a1 = 0.0f;
        const int p0 = g_rowptr[i];
        const int p1 = g_rowptr[i + 1];
        // software-pipelined gather (2-deep), two streams per nnz
        int p = p0;
        if (p < p1) {
            float v = g_val[p];
            int   c = g_col[p];
            for (++p; p < p1; ++p) {
                const float vn = g_val[p];
                const int   cn = g_col[p];
                a0 = fmaf(v, __ldg(&inp [c * HH + m]), a0);
                a1 = fmaf(v, __ldg(&h_in[c * HH + m]), a1);
                v = vn; c = cn;
            }
            a0 = fmaf(v, __ldg(&inp [c * HH + m]), a0);
            a1 = fmaf(v, __ldg(&h_in[c * HH + m]), a1);
        }
        sAi[r][m] = a0;
        sAh[r][m] = a1;
    }
    __syncthreads();

    const int kk = m;
    const int rbase = rg * 8;

    float ai[8], af[8], ao[8], ag[8];
    {
        const float b0 = __ldg(&bgi[kk      ]) + __ldg(&bgh[kk      ]) + __ldg(&bli[kk      ]) + __ldg(&blh[kk      ]);
        const float b1 = __ldg(&bgi[kk +  64]) + __ldg(&bgh[kk +  64]) + __ldg(&bli[kk +  64]) + __ldg(&blh[kk +  64]);
        const float b2 = __ldg(&bgi[kk + 128]) + __ldg(&bgh[kk + 128]) + __ldg(&bli[kk + 128]) + __ldg(&blh[kk + 128]);
        const float b3 = __ldg(&bgi[kk + 192]) + __ldg(&bgh[kk + 192]) + __ldg(&bli[kk + 192]) + __ldg(&blh[kk + 192]);
#pragma unroll
        for (int r = 0; r < 8; ++r) { ai[r] = b0; af[r] = b1; ao[r] = b2; ag[r] = b3; }
    }

#define ACC_MAT(W, S)                                                       \
    _Pragma("unroll 4")                                                     \
    for (int mm = 0; mm < HH; ++mm) {                                       \
        const float w0 = __ldg(&W[mm * G4 + kk      ]);                     \
        const float w1 = __ldg(&W[mm * G4 + kk +  64]);                     \
        const float w2 = __ldg(&W[mm * G4 + kk + 128]);                     \
        const float w3 = __ldg(&W[mm * G4 + kk + 192]);                     \
        _Pragma("unroll")                                                   \
        for (int r = 0; r < 8; ++r) {                                       \
            const float v = S[rbase + r][mm];                               \
            ai[r] = fmaf(v, w0, ai[r]); af[r] = fmaf(v, w1, af[r]);         \
            ao[r] = fmaf(v, w2, ao[r]); ag[r] = fmaf(v, w3, ag[r]);         \
        }                                                                   \
    }

    ACC_MAT(Wgi, sAi)
    ACC_MAT(Wgh, sAh)
    ACC_MAT(Wli, sI)
    ACC_MAT(Wlh, sH)
#undef ACC_MAT

#pragma unroll
    for (int r = 0; r < 8; ++r) {
        const int i = row0 + rbase + r;
        const float cold = __ldg(&c_in[i * HH + kk]);
        const float igt = sigm(ai[r]);
        const float fgt = sigm(af[r]);
        const float ogt = sigm(ao[r]);
        const float ggt = tanhf(ag[r]);
        const float cn = fgt * cold + igt * ggt;
        c_out[i * HH + kk] = cn;
        h_out[i * HH + kk] = ogt * tanhf(cn);
    }
}

// Final projection: out[i,p] = h1[i,:] @ outW[:,p] + outb[p]
__global__ void out_kernel(const float* __restrict__ outW,
                           const float* __restrict__ outb,
                           float* __restrict__ out)
{
    const int idx = blockIdx.x * blockDim.x + threadIdx.x;
    if (idx >= NN * PP) return;
    const int i = idx / PP;
    const int p = idx % PP;
    const float* h = &g_h1[0][i * HH];   // final parity: buffer 0 after T=48 steps
    float acc = __ldg(&outb[p]);
#pragma unroll
    for (int mm = 0; mm < HH; ++mm)
        acc = fmaf(h[mm], __ldg(&outW[mm * PP + p]), acc);
    out[idx] = acc;
}

// ---------------- launch --------------------------------------------------------
extern "C" void kernel_launch(void* const* d_in, const int* in_sizes, int n_in,
                              void* d_out, int out_size) {
    const float* x     = (const float*)d_in[0];
    const float* adj   = (const float*)d_in[1];
    const float* gcWi0 = (const float*)d_in[2];  const float* gcbi0 = (const float*)d_in[3];
    const float* gcWh0 = (const float*)d_in[4];  const float* gcbh0 = (const float*)d_in[5];
    const float* liWi0 = (const float*)d_in[6];  const float* libi0 = (const float*)d_in[7];
    const float* liWh0 = (const float*)d_in[8];  const float* libh0 = (const float*)d_in[9];
    const float* gcWi1 = (const float*)d_in[10]; const float* gcbi1 = (const float*)d_in[11];
    const float* gcWh1 = (const float*)d_in[12]; const float* gcbh1 = (const float*)d_in[13];
    const float* liWi1 = (const float*)d_in[14]; const float* libi1 = (const float*)d_in[15];
    const float* liWh1 = (const float*)d_in[16]; const float* libh1 = (const float*)d_in[17];
    const float* outW  = (const float*)d_in[18]; const float* outb  = (const float*)d_in[19];
    float* out = (float*)d_out;

    // Preprocessing (captured in the graph; deterministic)
    degree_kernel<<<NN, 128>>>(adj);
    scan_kernel<<<1, 1024>>>();
    fill_kernel<<<(NN * 32 + 255) / 256, 256>>>(adj);
    xT_kernel<<<(NN * 96 + 255) / 256, 256>>>(x);
    ax_kernel<<<NN, 96>>>();
    zero_kernel<<<(NN * HH + 255) / 256, 256>>>();

    // Recurrence: 2 fused kernels per timestep
    for (int t = 0; t < TT; ++t) {
        const int rd = t & 1;
        cell0_kernel<<<NN / RTILE, 256>>>(t, rd,
            gcWi0, gcWh0, liWi0, liWh0, gcbi0, gcbh0, libi0, libh0);
        cell1_kernel<<<NN / RTILE, 256>>>(rd,
            gcWi1, gcWh1, liWi1, liWh1, gcbi1, gcbh1, libi1, libh1);
    }

    out_kernel<<<(NN * PP + 255) / 256, 256>>>(outW, outb, out);
}